// round 11
// baseline (speedup 1.0000x reference)
#include <cuda_runtime.h>
#include <cuda_fp16.h>
#include <math.h>

#define NMAX 50000
#define DDIM 64

// fp16 copy of transformed features (gather side of the scatter)
__device__ __half g_hh[(size_t)NMAX * DDIM];

// ---------------------------------------------------------------------------
// Kernel 1: h = X @ W^T ; out = h*skip + bias (fp32) ; g_hh = h (fp16)
// 128 rows x 64 cols per block, 8x4 register tile per thread.
// W tile in smem (transposed); X read directly from gmem (warp-broadcast
// float4 loads, MLP=8) -> smem 51KB -> 17.4KB, occupancy doubles.
// ---------------------------------------------------------------------------
#define WSTR 68

__global__ void __launch_bounds__(256) gemm_skip_kernel(
    const float* __restrict__ X, const float* __restrict__ W,
    const float* __restrict__ bias, const float* __restrict__ skipw,
    float* __restrict__ out, int n)
{
    __shared__ float sW[DDIM * WSTR];   // sW[d*WSTR + o] = W[o][d]

    const int tid  = threadIdx.x;
    const int row0 = blockIdx.x * 128;

    #pragma unroll
    for (int i = 0; i < 16; i++) {
        int idx = tid + i * 256;
        int o = idx >> 6, d = idx & 63;
        sW[d * WSTR + o] = W[idx];
    }
    __syncthreads();

    const int tx = tid & 15;
    const int ty = tid >> 4;
    const int o0 = tx * 4;
    const int r0 = row0 + ty * 8;

    // clamped row indices: OOB rows load row n-1 (results discarded at store)
    const float* xrow[8];
    #pragma unroll
    for (int i = 0; i < 8; i++) {
        int r = r0 + i;
        xrow[i] = X + (size_t)((r < n) ? r : (n - 1)) * DDIM;
    }

    float acc[8][4];
    #pragma unroll
    for (int i = 0; i < 8; i++)
        #pragma unroll
        for (int j = 0; j < 4; j++) acc[i][j] = 0.0f;

    #pragma unroll 2
    for (int d4 = 0; d4 < DDIM; d4 += 4) {
        float4 xv[8];
        #pragma unroll
        for (int i = 0; i < 8; i++)
            xv[i] = *reinterpret_cast<const float4*>(xrow[i] + d4);

        #pragma unroll
        for (int j = 0; j < 4; j++) {
            float4 wv = *reinterpret_cast<const float4*>(&sW[(d4 + j) * WSTR + o0]);
            #pragma unroll
            for (int i = 0; i < 8; i++) {
                float xs = (j == 0) ? xv[i].x : (j == 1) ? xv[i].y
                         : (j == 2) ? xv[i].z : xv[i].w;
                acc[i][0] = fmaf(xs, wv.x, acc[i][0]);
                acc[i][1] = fmaf(xs, wv.y, acc[i][1]);
                acc[i][2] = fmaf(xs, wv.z, acc[i][2]);
                acc[i][3] = fmaf(xs, wv.w, acc[i][3]);
            }
        }
    }

    const float4 swv = *reinterpret_cast<const float4*>(&skipw[o0]);
    const float4 bvv = *reinterpret_cast<const float4*>(&bias[o0]);

    #pragma unroll
    for (int i = 0; i < 8; i++) {
        int gr = r0 + i;
        if (gr < n) {
            float4 hv = make_float4(acc[i][0], acc[i][1], acc[i][2], acc[i][3]);
            __half2* dst2 = reinterpret_cast<__half2*>(&g_hh[(size_t)gr * DDIM + o0]);
            dst2[0] = __float22half2_rn(make_float2(hv.x, hv.y));
            dst2[1] = __float22half2_rn(make_float2(hv.z, hv.w));
            float4 ov;
            ov.x = fmaf(hv.x, swv.x, bvv.x);
            ov.y = fmaf(hv.y, swv.y, bvv.y);
            ov.z = fmaf(hv.z, swv.z, bvv.z);
            ov.w = fmaf(hv.w, swv.w, bvv.w);
            *reinterpret_cast<float4*>(&out[(size_t)gr * DDIM + o0]) = ov;
        }
    }
}

// ---------------------------------------------------------------------------
// Kernel 2: out[dst] += h_fp16[src] * w   via red.global.add.v4.f32
// Edge metadata staged in smem (coalesced once), 16 lanes/edge, one red.v4
// per lane. LTS atomic-message-rate bound (~33us floor at 12.8M messages).
// ---------------------------------------------------------------------------
#define EPB 256

__global__ void __launch_bounds__(256) scatter_kernel(
    const float* __restrict__ ew,
    const int*   __restrict__ src,
    const int*   __restrict__ dst,
    float* __restrict__ out,
    int E)
{
    __shared__ int   es[EPB];
    __shared__ int   ed[EPB];
    __shared__ float ewt[EPB];

    const int tid  = threadIdx.x;
    const int base = blockIdx.x * EPB;

    int ge = base + tid;
    if (ge < E) {
        es[tid]  = src[ge];
        ed[tid]  = dst[ge];
        ewt[tid] = ew[ge];
    }
    __syncthreads();

    const int lane4 = (tid & 15) << 2;   // 0,4,...,60 (4 floats per lane)
    const int esub  = tid >> 4;          // 0..15

    #pragma unroll
    for (int p = 0; p < 16; p++) {
        int e = p * 16 + esub;
        if (base + e >= E) break;
        int   s = es[e];
        int   d = ed[e];
        float w = ewt[e];

        const uint2 pk = *reinterpret_cast<const uint2*>(
            &g_hh[(size_t)s * DDIM + lane4]);
        float2 f0 = __half22float2(*reinterpret_cast<const __half2*>(&pk.x));
        float2 f1 = __half22float2(*reinterpret_cast<const __half2*>(&pk.y));

        float* o = out + (size_t)d * DDIM + lane4;
        asm volatile(
            "red.global.add.v4.f32 [%0], {%1, %2, %3, %4};"
            :: "l"(o), "f"(f0.x * w), "f"(f0.y * w), "f"(f1.x * w), "f"(f1.y * w)
            : "memory");
    }
}

// ---------------------------------------------------------------------------
// Kernel 3: in-place SELU
// ---------------------------------------------------------------------------
__global__ void __launch_bounds__(256) selu_kernel(float* __restrict__ out, int total4)
{
    const float scale = 1.0507009873554805f;
    const float alpha = 1.6732632423543772f;
    int i = blockIdx.x * blockDim.x + threadIdx.x;
    if (i >= total4) return;
    float4 v = reinterpret_cast<float4*>(out)[i];
    v.x = v.x > 0.0f ? scale * v.x : scale * alpha * (expf(v.x) - 1.0f);
    v.y = v.y > 0.0f ? scale * v.y : scale * alpha * (expf(v.y) - 1.0f);
    v.z = v.z > 0.0f ? scale * v.z : scale * alpha * (expf(v.z) - 1.0f);
    v.w = v.w > 0.0f ? scale * v.w : scale * alpha * (expf(v.w) - 1.0f);
    reinterpret_cast<float4*>(out)[i] = v;
}

extern "C" void kernel_launch(void* const* d_in, const int* in_sizes, int n_in,
                              void* d_out, int out_size)
{
    const float* features = (const float*)d_in[0];
    const float* W        = (const float*)d_in[1];
    const float* bias     = (const float*)d_in[2];
    const float* skipw    = (const float*)d_in[3];
    const float* ew       = (const float*)d_in[4];
    const int*   esrc     = (const int*)d_in[5];
    const int*   edst     = (const int*)d_in[6];
    float* out = (float*)d_out;

    const int n = in_sizes[0] / DDIM;     // 50000
    const int E = in_sizes[4];            // 800000

    // 1. GEMM + skip/bias accumulator init + fp16 copy
    gemm_skip_kernel<<<(n + 127) / 128, 256>>>(features, W, bias, skipw, out, n);

    // 2. edge-parallel scatter (16 threads/edge, staged meta)
    int sblocks = (E + EPB - 1) / EPB;
    scatter_kernel<<<sblocks, 256>>>(ew, esrc, edst, out, E);

    // 3. SELU in place
    int total4 = (n * DDIM) / 4;
    selu_kernel<<<(total4 + 255) / 256, 256>>>(out, total4);
}

// round 12
// speedup vs baseline: 1.0821x; 1.0821x over previous
#include <cuda_runtime.h>
#include <cuda_fp16.h>
#include <math.h>

#define NMAX 50000
#define DDIM 64

// fp16 copy of transformed features (gather side of the scatter)
__device__ __half g_hh[(size_t)NMAX * DDIM];

// packed f32x2 FMA (FFMA2) — ptxas never emits this from C++; PTX-only.
#define FMA_F32X2(acc, a, b) \
    asm("fma.rn.f32x2 %0, %1, %2, %0;" : "+l"(acc) : "l"(a), "l"(b))
#define PACK_F32X2(out, lo, hi) \
    asm("mov.b64 %0, {%1, %2};" : "=l"(out) : "r"(lo), "r"(hi))
#define UNPACK_F32X2(lo, hi, in) \
    asm("mov.b64 {%0, %1}, %2;" : "=r"(lo), "=r"(hi) : "l"(in))

// ---------------------------------------------------------------------------
// Kernel 1: h = X @ W^T ; out = h*skip + bias (fp32) ; g_hh = h (fp16)
// 128 rows x 64 cols per block, 8x4 register tile per thread.
// R10 smem structure (X+W tiles) + f32x2 packed accumulation (16 FFMA2/d
// instead of 32 FFMA/d; identical fp32 numerics).
// ---------------------------------------------------------------------------
#define XSTR 132
#define WSTR 68

__global__ void __launch_bounds__(256) gemm_skip_kernel(
    const float* __restrict__ X, const float* __restrict__ W,
    const float* __restrict__ bias, const float* __restrict__ skipw,
    float* __restrict__ out, int n)
{
    __shared__ float sW[DDIM * WSTR];   // sW[d*WSTR + o] = W[o][d]
    __shared__ float sX[DDIM * XSTR];   // sX[d*XSTR + r]

    const int tid  = threadIdx.x;
    const int row0 = blockIdx.x * 128;

    #pragma unroll
    for (int i = 0; i < 16; i++) {
        int idx = tid + i * 256;
        int o = idx >> 6, d = idx & 63;
        sW[d * WSTR + o] = W[idx];
    }
    #pragma unroll
    for (int i = 0; i < 32; i++) {
        int idx = tid + i * 256;
        int r = idx >> 6, d = idx & 63;
        int gr = row0 + r;
        sX[d * XSTR + r] = (gr < n) ? X[(size_t)gr * DDIM + d] : 0.0f;
    }
    __syncthreads();

    const int tx = tid & 15;
    const int ty = tid >> 4;
    const int o0 = tx * 4;
    const int r0 = ty * 8;

    // accp[i][p]: packed pair of columns (o0+2p, o0+2p+1) for row r0+i
    unsigned long long accp[8][2];
    #pragma unroll
    for (int i = 0; i < 8; i++) {
        accp[i][0] = 0ULL;
        accp[i][1] = 0ULL;
    }

    #pragma unroll 16
    for (int d = 0; d < DDIM; d++) {
        float4 xa = *reinterpret_cast<const float4*>(&sX[d * XSTR + r0]);
        float4 xb = *reinterpret_cast<const float4*>(&sX[d * XSTR + r0 + 4]);
        // w pair-packed: one LDS.128 = two f32x2 operands
        ulonglong2 wp = *reinterpret_cast<const ulonglong2*>(&sW[d * WSTR + o0]);
        float x[8] = {xa.x, xa.y, xa.z, xa.w, xb.x, xb.y, xb.z, xb.w};
        #pragma unroll
        for (int i = 0; i < 8; i++) {
            unsigned xu = __float_as_uint(x[i]);
            unsigned long long xx;
            PACK_F32X2(xx, xu, xu);
            FMA_F32X2(accp[i][0], xx, wp.x);
            FMA_F32X2(accp[i][1], xx, wp.y);
        }
    }

    const float4 swv = *reinterpret_cast<const float4*>(&skipw[o0]);
    const float4 bvv = *reinterpret_cast<const float4*>(&bias[o0]);

    #pragma unroll
    for (int i = 0; i < 8; i++) {
        int gr = row0 + r0 + i;
        if (gr < n) {
            unsigned u0, u1, u2, u3;
            UNPACK_F32X2(u0, u1, accp[i][0]);
            UNPACK_F32X2(u2, u3, accp[i][1]);
            float4 hv = make_float4(__uint_as_float(u0), __uint_as_float(u1),
                                    __uint_as_float(u2), __uint_as_float(u3));
            __half2* dst2 = reinterpret_cast<__half2*>(&g_hh[(size_t)gr * DDIM + o0]);
            dst2[0] = __float22half2_rn(make_float2(hv.x, hv.y));
            dst2[1] = __float22half2_rn(make_float2(hv.z, hv.w));
            float4 ov;
            ov.x = fmaf(hv.x, swv.x, bvv.x);
            ov.y = fmaf(hv.y, swv.y, bvv.y);
            ov.z = fmaf(hv.z, swv.z, bvv.z);
            ov.w = fmaf(hv.w, swv.w, bvv.w);
            *reinterpret_cast<float4*>(&out[(size_t)gr * DDIM + o0]) = ov;
        }
    }
}

// ---------------------------------------------------------------------------
// Kernel 2: out[dst] += h_fp16[src] * w   via red.global.add.v4.f32
// Edge metadata staged in smem, 16 lanes/edge, one red.v4 per lane.
// LTS atomic-message-rate bound (~33us floor at 12.8M messages).
// ---------------------------------------------------------------------------
#define EPB 256

__global__ void __launch_bounds__(256) scatter_kernel(
    const float* __restrict__ ew,
    const int*   __restrict__ src,
    const int*   __restrict__ dst,
    float* __restrict__ out,
    int E)
{
    __shared__ int   es[EPB];
    __shared__ int   ed[EPB];
    __shared__ float ewt[EPB];

    const int tid  = threadIdx.x;
    const int base = blockIdx.x * EPB;

    int ge = base + tid;
    if (ge < E) {
        es[tid]  = src[ge];
        ed[tid]  = dst[ge];
        ewt[tid] = ew[ge];
    }
    __syncthreads();

    const int lane4 = (tid & 15) << 2;   // 0,4,...,60
    const int esub  = tid >> 4;          // 0..15

    #pragma unroll
    for (int p = 0; p < 16; p++) {
        int e = p * 16 + esub;
        if (base + e >= E) break;
        int   s = es[e];
        int   d = ed[e];
        float w = ewt[e];

        const uint2 pk = *reinterpret_cast<const uint2*>(
            &g_hh[(size_t)s * DDIM + lane4]);
        float2 f0 = __half22float2(*reinterpret_cast<const __half2*>(&pk.x));
        float2 f1 = __half22float2(*reinterpret_cast<const __half2*>(&pk.y));

        float* o = out + (size_t)d * DDIM + lane4;
        asm volatile(
            "red.global.add.v4.f32 [%0], {%1, %2, %3, %4};"
            :: "l"(o), "f"(f0.x * w), "f"(f0.y * w), "f"(f1.x * w), "f"(f1.y * w)
            : "memory");
    }
}

// ---------------------------------------------------------------------------
// Kernel 3: in-place SELU
// ---------------------------------------------------------------------------
__global__ void __launch_bounds__(256) selu_kernel(float* __restrict__ out, int total4)
{
    const float scale = 1.0507009873554805f;
    const float alpha = 1.6732632423543772f;
    int i = blockIdx.x * blockDim.x + threadIdx.x;
    if (i >= total4) return;
    float4 v = reinterpret_cast<float4*>(out)[i];
    v.x = v.x > 0.0f ? scale * v.x : scale * alpha * (expf(v.x) - 1.0f);
    v.y = v.y > 0.0f ? scale * v.y : scale * alpha * (expf(v.y) - 1.0f);
    v.z = v.z > 0.0f ? scale * v.z : scale * alpha * (expf(v.z) - 1.0f);
    v.w = v.w > 0.0f ? scale * v.w : scale * alpha * (expf(v.w) - 1.0f);
    reinterpret_cast<float4*>(out)[i] = v;
}

extern "C" void kernel_launch(void* const* d_in, const int* in_sizes, int n_in,
                              void* d_out, int out_size)
{
    const float* features = (const float*)d_in[0];
    const float* W        = (const float*)d_in[1];
    const float* bias     = (const float*)d_in[2];
    const float* skipw    = (const float*)d_in[3];
    const float* ew       = (const float*)d_in[4];
    const int*   esrc     = (const int*)d_in[5];
    const int*   edst     = (const int*)d_in[6];
    float* out = (float*)d_out;

    const int n = in_sizes[0] / DDIM;     // 50000
    const int E = in_sizes[4];            // 800000

    // 1. GEMM + skip/bias accumulator init + fp16 copy
    gemm_skip_kernel<<<(n + 127) / 128, 256>>>(features, W, bias, skipw, out, n);

    // 2. edge-parallel scatter (16 threads/edge, staged meta)
    int sblocks = (E + EPB - 1) / EPB;
    scatter_kernel<<<sblocks, 256>>>(ew, esrc, edst, out, E);

    // 3. SELU in place
    int total4 = (n * DDIM) / 4;
    selu_kernel<<<(total4 + 255) / 256, 256>>>(out, total4);
}